// round 16
// baseline (speedup 1.0000x reference)
#include <cuda_runtime.h>
#include <cstdint>
#include <cstddef>

typedef unsigned long long ull;

#define TS 2048
#define Y1_ELEMS ((size_t)TS * 64 * 256)

// scratch (allocation-free rule)
__device__ float g_gx[(size_t)TS * 64 * 1024];
__device__ float g_y0[(size_t)TS * 64 * 256];
// h exchange through L2: [buf][group][k][batch]
__device__ float g_hx[2][16][256][4];
// per-layer, per-group, per-rank flag LINES; 8 per-warp words per line
__device__ __align__(128) unsigned g_flag[2][16][8][32];
__device__ __align__(128) unsigned g_fin[2][16][32];

__device__ __forceinline__ ull fma2(ull a, ull b, ull c) {
    ull d; asm("fma.rn.f32x2 %0,%1,%2,%3;" : "=l"(d) : "l"(a), "l"(b), "l"(c)); return d;
}
__device__ __forceinline__ ull mul2(ull a, ull b) {
    ull d; asm("mul.rn.f32x2 %0,%1,%2;" : "=l"(d) : "l"(a), "l"(b)); return d;
}
__device__ __forceinline__ ull add2(ull a, ull b) {
    ull d; asm("add.rn.f32x2 %0,%1,%2;" : "=l"(d) : "l"(a), "l"(b)); return d;
}
__device__ __forceinline__ ull pk(float lo, float hi) {
    ull r; asm("mov.b64 %0,{%1,%2};" : "=l"(r) : "f"(lo), "f"(hi)); return r;
}
__device__ __forceinline__ void upk(ull a, float& x, float& y) {
    asm("mov.b64 {%0,%1},%2;" : "=f"(x), "=f"(y) : "l"(a));
}
__device__ __forceinline__ ull dup2(float x) {
    ull r; asm("mov.b64 %0,{%1,%1};" : "=l"(r) : "f"(x)); return r;
}
__device__ __forceinline__ float ex2f(float x) {
    float r; asm("ex2.approx.f32 %0,%1;" : "=f"(r) : "f"(x)); return r;
}
__device__ __forceinline__ float rcpf(float x) {
    float r; asm("rcp.approx.f32 %0,%1;" : "=f"(r) : "f"(x)); return r;
}
__device__ __forceinline__ float sigf(float x) {
    return rcpf(1.f + ex2f(-1.44269504f * x));
}
__device__ __forceinline__ float tanhap(float x) {
    float r; asm("tanh.approx.f32 %0,%1;" : "=f"(r) : "f"(x)); return r;
}
__device__ __forceinline__ unsigned ldacq(const unsigned* p) {
    unsigned v;
    asm volatile("ld.acquire.gpu.global.u32 %0,[%1];" : "=r"(v) : "l"(p) : "memory");
    return v;
}
__device__ __forceinline__ unsigned t32(float x) {
    unsigned r; asm("cvt.rna.tf32.f32 %0,%1;" : "=r"(r) : "f"(x)); return r;
}
__device__ __forceinline__ void mma8(float* c, const unsigned* a, const unsigned* b) {
    asm volatile(
        "mma.sync.aligned.m16n8k8.row.col.f32.tf32.tf32.f32 "
        "{%0,%1,%2,%3},{%4,%5,%6,%7},{%8,%9},{%0,%1,%2,%3};"
        : "+f"(c[0]), "+f"(c[1]), "+f"(c[2]), "+f"(c[3])
        : "r"(a[0]), "r"(a[1]), "r"(a[2]), "r"(a[3]), "r"(b[0]), "r"(b[1]));
}

// ---------------------------------------------------------------------------
// tf32 tensor-core GEMM (verbatim R14): g_gx[m][n] = A_row(m).W[:,n] + bias[n]
// mode 0: A_row(m) = x + ((m&63)*TS + (m>>6))*128, K=128
// mode 1: A_row(m) = g_y0 + m*256,                 K=256
// ---------------------------------------------------------------------------
__global__ void __launch_bounds__(256)
gemm_k(const float* __restrict__ A, const float* __restrict__ W,
       const float* __restrict__ bias, int K, int mode)
{
    __shared__ float As[128][36];
    __shared__ float Bs[32][136];

    const int tid  = threadIdx.x;
    const int lane = tid & 31;
    const int wid  = tid >> 5;
    const int wm   = wid & 1;
    const int wn   = wid >> 1;
    const int n0   = blockIdx.x * 128;
    const int m0   = blockIdx.y * 128;

    const int ar = tid >> 1, ak = (tid & 1) * 16;
    const int m = m0 + ar;
    const float* arow = mode ? (g_y0 + (size_t)m * 256)
                             : (A + ((size_t)(m & 63) * TS + (m >> 6)) * 128);
    const int bk = tid >> 3, bn = (tid & 7) * 16;
    const float* wrow = W + (size_t)bk * 1024 + n0 + bn;

    float acc[16][4];
#pragma unroll
    for (int i = 0; i < 16; ++i)
#pragma unroll
        for (int j = 0; j < 4; ++j) acc[i][j] = 0.f;

    float4 av[4], bv[4];
#pragma unroll
    for (int q = 0; q < 4; ++q) {
        av[q] = *(const float4*)(arow + ak + 4 * q);
        bv[q] = *(const float4*)(wrow + 4 * q);
    }

#pragma unroll 1
    for (int k0 = 0; k0 < K; k0 += 32) {
        __syncthreads();
#pragma unroll
        for (int q = 0; q < 4; ++q) {
            *(float4*)&As[ar][ak + 4 * q] = av[q];
            *(float4*)&Bs[bk][bn + 4 * q] = bv[q];
        }
        __syncthreads();

        if (k0 + 32 < K) {
#pragma unroll
            for (int q = 0; q < 4; ++q) {
                av[q] = *(const float4*)(arow + k0 + 32 + ak + 4 * q);
                bv[q] = *(const float4*)(wrow + (size_t)(k0 + 32) * 1024 + 4 * q);
            }
        }

#pragma unroll
        for (int k8 = 0; k8 < 32; k8 += 8) {
            unsigned af[4][4], bf[4][2];
            const int kk = k8 + (lane & 3);
#pragma unroll
            for (int i = 0; i < 4; ++i) {
                const int row = wm * 64 + i * 16 + (lane >> 2);
                af[i][0] = t32(As[row][kk]);
                af[i][1] = t32(As[row + 8][kk]);
                af[i][2] = t32(As[row][kk + 4]);
                af[i][3] = t32(As[row + 8][kk + 4]);
            }
#pragma unroll
            for (int j = 0; j < 4; ++j) {
                const int col = wn * 32 + j * 8 + (lane >> 2);
                bf[j][0] = t32(Bs[kk][col]);
                bf[j][1] = t32(Bs[kk + 4][col]);
            }
#pragma unroll
            for (int i = 0; i < 4; ++i)
#pragma unroll
                for (int j = 0; j < 4; ++j)
                    mma8(acc[i * 4 + j], af[i], bf[j]);
        }
    }

#pragma unroll
    for (int j = 0; j < 4; ++j) {
        const int col = n0 + wn * 32 + j * 8 + 2 * (lane & 3);
        float2 bb = *(const float2*)&bias[col];
#pragma unroll
        for (int i = 0; i < 4; ++i) {
            const int row = m0 + wm * 64 + i * 16 + (lane >> 2);
            const float* c = acc[i * 4 + j];
            float2 v0 = make_float2(c[0] + bb.x, c[1] + bb.y);
            float2 v1 = make_float2(c[2] + bb.x, c[3] + bb.y);
            *(float2*)&g_gx[(size_t)row * 1024 + col] = v0;
            *(float2*)&g_gx[(size_t)(row + 8) * 1024 + col] = v1;
        }
    }
}

// ---------------------------------------------------------------------------
// Recurrence (R15 + per-warp publish):
// 128 CTAs; group g = blockIdx>>3 (8 CTAs), rank r = blockIdx&7.
// Group handles batches [g*4, g*4+4). Rank owns units [r*32, r*32+32).
// Chunk i = source rank (r+i)&7; chunk 0 = OWN rank from smem hsm.
// PER-WARP flags: warp w of rank r releases flag[r][w] immediately after
// its own gather+STG+syncwarp — the CTA __syncthreads (needed only to order
// hsm for next step's chunk 0) moves AFTER the release, off the inter-CTA
// critical path. Consumers poll all 56 remote warp flags with ld.acquire.v4
// (lanes 0..13, 4 flags per load). Matvec order: poll -> 7 hoisted ldcgs ->
// chunk-0 fma from smem (covers load latency) -> chunks 1..7.
// ---------------------------------------------------------------------------
__global__ void __launch_bounds__(256, 1)
recur_k(const float* __restrict__ whh, float* __restrict__ out, int layer)
{
    __shared__ __align__(16) float hsm[2][32][4];   // own-rank h [buf][ul][b]

    const int tid  = threadIdx.x;
    const int w    = tid >> 5;
    const int lane = tid & 31;
    const int grp  = blockIdx.x >> 3;
    const int r    = blockIdx.x & 7;
    const int gb0  = grp * 4;

    // epilogue identity
    const int cp = lane >> 2;          // col-pair 0..7
    const int b  = lane & 3;           // batch 0..3
    const int gp = cp & 1;             // 0 -> (f,i), 1 -> (o,g)
    const int u  = cp >> 1;            // unit-local in warp 0..3
    const int jj = r * 32 + w * 4 + u;
    const int colA = (2 * gp) * 256 + jj;

    // weights: wreg[i][cp] for k = ((r+i)&7)*32 + lane, cols (cA, cA+256)
    ull wreg[8][8];
#pragma unroll
    for (int i = 0; i < 8; ++i) {
        const int k = ((r + i) & 7) * 32 + lane;
#pragma unroll
        for (int cpi = 0; cpi < 8; ++cpi) {
            const int cA = (2 * (cpi & 1)) * 256 + r * 32 + w * 4 + (cpi >> 1);
            const float* wp = whh + (size_t)k * 1024 + cA;
            wreg[i][cpi] = pk(wp[0], wp[256]);
        }
    }

    // poll identity: lanes 0..13 -> (remote rank, flag quad)
    const int prr = (r + 1 + (lane >> 1)) & 7;
    const unsigned* pfp = &g_flag[layer][grp][prr][(lane & 1) * 4];

    unsigned* myflag = &g_flag[layer][grp][r][w];
    unsigned* fin    = &g_fin[layer][grp][0];

    float cst = 0.f;
    float* yout = layer ? out : g_y0;
    float* hn = out + Y1_ELEMS + (size_t)layer * 16384;
    float* cn = out + Y1_ELEMS + 32768 + (size_t)layer * 16384;

    // zero hsm (both buffers); step-0 matvec reads zeros
    ((float*)hsm)[tid] = 0.f;
    __syncthreads();

    // gates_x pipeline
    ull gxr, gxn = 0ull;
    {
        const float* gpx = g_gx + ((size_t)(TS - 1) * 64 + gb0 + b) * 1024 + colA;
        gxr = pk(__ldg(gpx), __ldg(gpx + 256));
    }

#pragma unroll 1
    for (int s = 0; s < TS; ++s) {
        const int cur = s & 1;
        const int nxt = cur ^ 1;

        if (s + 1 < TS) {
            const float* gpx = g_gx + ((size_t)(TS - 2 - s) * 64 + gb0 + b) * 1024 + colA;
            gxn = pk(__ldg(gpx), __ldg(gpx + 256));
        }

        // per-warp wait: lanes 0..13 poll 4 remote warp-flags each (v4)
        if (s) {
            if (lane < 14) {
                const unsigned tgt = (unsigned)s;
                unsigned fa, fb, fc, fd;
#pragma unroll 1
                do {
                    asm volatile("ld.acquire.gpu.global.v4.u32 {%0,%1,%2,%3},[%4];"
                                 : "=r"(fa), "=r"(fb), "=r"(fc), "=r"(fd)
                                 : "l"(pfp) : "memory");
                } while (fa < tgt || fb < tgt || fc < tgt || fd < tgt);
            }
            __syncwarp();
        }

        // hoisted remote loads (MLP=7), then chunk-0 fma covers their latency
        float4 h4a[7];
#pragma unroll
        for (int i = 0; i < 7; ++i) {
            h4a[i] = make_float4(0.f, 0.f, 0.f, 0.f);
            if (s) h4a[i] = __ldcg((const float4*)&g_hx[cur][grp][((r + 1 + i) & 7) * 32 + lane][0]);
        }

        ull v[32];
        // chunk 0: OWN rank from smem (ordered by end-of-prev-step bar)
        {
            float4 h4 = *(const float4*)&hsm[cur][lane][0];
            ull hd0 = dup2(h4.x), hd1 = dup2(h4.y), hd2 = dup2(h4.z), hd3 = dup2(h4.w);
#pragma unroll
            for (int cpi = 0; cpi < 8; ++cpi) {
                v[cpi * 4 + 0] = mul2(hd0, wreg[0][cpi]);
                v[cpi * 4 + 1] = mul2(hd1, wreg[0][cpi]);
                v[cpi * 4 + 2] = mul2(hd2, wreg[0][cpi]);
                v[cpi * 4 + 3] = mul2(hd3, wreg[0][cpi]);
            }
        }

        // chunks 1..7
#pragma unroll
        for (int i = 1; i < 8; ++i) {
            float4 h4 = h4a[i - 1];
            ull hd0 = dup2(h4.x), hd1 = dup2(h4.y), hd2 = dup2(h4.z), hd3 = dup2(h4.w);
#pragma unroll
            for (int cpi = 0; cpi < 8; ++cpi) {
                v[cpi * 4 + 0] = fma2(hd0, wreg[i][cpi], v[cpi * 4 + 0]);
                v[cpi * 4 + 1] = fma2(hd1, wreg[i][cpi], v[cpi * 4 + 1]);
                v[cpi * 4 + 2] = fma2(hd2, wreg[i][cpi], v[cpi * 4 + 2]);
                v[cpi * 4 + 3] = fma2(hd3, wreg[i][cpi], v[cpi * 4 + 3]);
            }
        }

        // reduce-scatter butterfly: lane l ends holding (cp=l>>2, b=l&3)
#pragma unroll
        for (int t = 0; t < 5; ++t) {
            const int mybit = (lane >> t) & 1;
            const int n = 32 >> t;
#pragma unroll
            for (int i = 0; i < 16; ++i) {
                if (i < (n >> 1)) {
                    ull lo = v[2 * i], hi = v[2 * i + 1];
                    ull send = mybit ? lo : hi;
                    ull recv = __shfl_xor_sync(0xffffffffu, send, 1 << t);
                    v[i] = add2(mybit ? hi : lo, recv);
                }
            }
        }

        // epilogue
        float h1 = 0.f;
        {
            float p0, p1;
            upk(add2(v[0], gxr), p0, p1);
            float a0 = sigf(p0);
            float a1 = gp ? tanhap(p1) : sigf(p1);
            ull other = __shfl_xor_sync(0xffffffffu, pk(a0, a1), 4);
            if (gp == 0) {
                float so, tg; upk(other, so, tg);
                cst = a0 * cst + a1 * tg;
                h1 = so * tanhap(cst);
            }
        }
        gxr = gxn;

        // per-warp publish: gather -> STG/STS -> syncwarp -> lane0 release
        {
            float4 hv;
            const int base = lane & 24;
            hv.x = __shfl_sync(0xffffffffu, h1, base);
            hv.y = __shfl_sync(0xffffffffu, h1, base + 1);
            hv.z = __shfl_sync(0xffffffffu, h1, base + 2);
            hv.w = __shfl_sync(0xffffffffu, h1, base + 3);
            if ((lane & 7) == 0 && s < TS - 1) {
                const int row = r * 32 + w * 4 + (lane >> 3);
                *(float4*)&g_hx[nxt][grp][row][0] = hv;            // 1 STG.128
                *(float4*)&hsm[nxt][w * 4 + (lane >> 3)][0] = hv;  // 1 STS.128
            }
        }
        __syncwarp();
        if (s < TS - 1 && lane == 0)
            asm volatile("st.release.gpu.global.u32 [%0], %1;"
                         :: "l"(myflag), "r"((unsigned)(s + 1)) : "memory");

        // CTA bar: orders hsm for next step's chunk 0 — LOCAL path only
        __syncthreads();

        // outputs — off the critical chain
        if (gp == 0) {
            yout[((size_t)s * 64 + gb0 + b) * 256 + jj] = h1;
            if (s == TS - 1) {
                size_t hi_ = (size_t)(gb0 + b) * 256 + jj;
                hn[hi_] = h1; cn[hi_] = cst;
            }
        }
    }

    // reset flags for the next graph replay (deterministic launches)
    __syncthreads();
    if (tid == 0) {
        asm volatile("red.release.gpu.global.add.u32 [%0], 1;" :: "l"(fin) : "memory");
        if (r == 0) {
#pragma unroll 1
            while (ldacq(fin) < 8u) { }
#pragma unroll
            for (int d = 0; d < 8; ++d)
#pragma unroll
                for (int q = 0; q < 8; ++q)
                    asm volatile("st.global.u32 [%0], %1;"
                                 :: "l"(&g_flag[layer][grp][d][q]), "r"(0u) : "memory");
            asm volatile("st.global.u32 [%0], %1;" :: "l"(fin), "r"(0u) : "memory");
        }
    }
}

extern "C" void kernel_launch(void* const* d_in, const int* in_sizes, int n_in,
                              void* d_out, int out_size)
{
    const float* x    = (const float*)d_in[0];
    const float* wih0 = (const float*)d_in[1];
    const float* whh0 = (const float*)d_in[2];
    const float* b0   = (const float*)d_in[3];
    const float* wih1 = (const float*)d_in[4];
    const float* whh1 = (const float*)d_in[5];
    const float* b1   = (const float*)d_in[6];
    float* out = (float*)d_out;

    dim3 gg(8, 1024);
    gemm_k<<<gg, 256>>>(x, wih0, b0, 128, 0);
    recur_k<<<128, 256>>>(whh0, out, 0);
    gemm_k<<<gg, 256>>>(x, wih1, b1, 256, 1);
    recur_k<<<128, 256>>>(whh1, out, 1);
}

// round 17
// speedup vs baseline: 4.1728x; 4.1728x over previous
#include <cuda_runtime.h>
#include <cstdint>
#include <cstddef>

typedef unsigned long long ull;

#define TS 2048
#define Y1_ELEMS ((size_t)TS * 64 * 256)

// scratch (allocation-free rule)
__device__ float g_gx[(size_t)TS * 64 * 1024];
__device__ float g_y0[(size_t)TS * 64 * 256];
// h exchange through L2: [buf][group][k][batch]
__device__ float g_hx[2][16][256][4];
// per-layer, per-group, PER-RANK monotonic flags (each on own 128B line)
__device__ __align__(128) unsigned g_flag[2][16][8][32];
__device__ __align__(128) unsigned g_fin[2][16][32];

__device__ __forceinline__ ull fma2(ull a, ull b, ull c) {
    ull d; asm("fma.rn.f32x2 %0,%1,%2,%3;" : "=l"(d) : "l"(a), "l"(b), "l"(c)); return d;
}
__device__ __forceinline__ ull mul2(ull a, ull b) {
    ull d; asm("mul.rn.f32x2 %0,%1,%2;" : "=l"(d) : "l"(a), "l"(b)); return d;
}
__device__ __forceinline__ ull add2(ull a, ull b) {
    ull d; asm("add.rn.f32x2 %0,%1,%2;" : "=l"(d) : "l"(a), "l"(b)); return d;
}
__device__ __forceinline__ ull pk(float lo, float hi) {
    ull r; asm("mov.b64 %0,{%1,%2};" : "=l"(r) : "f"(lo), "f"(hi)); return r;
}
__device__ __forceinline__ void upk(ull a, float& x, float& y) {
    asm("mov.b64 {%0,%1},%2;" : "=f"(x), "=f"(y) : "l"(a));
}
__device__ __forceinline__ ull dup2(float x) {
    ull r; asm("mov.b64 %0,{%1,%1};" : "=l"(r) : "f"(x)); return r;
}
__device__ __forceinline__ float ex2f(float x) {
    float r; asm("ex2.approx.f32 %0,%1;" : "=f"(r) : "f"(x)); return r;
}
__device__ __forceinline__ float rcpf(float x) {
    float r; asm("rcp.approx.f32 %0,%1;" : "=f"(r) : "f"(x)); return r;
}
__device__ __forceinline__ float sigf(float x) {
    return rcpf(1.f + ex2f(-1.44269504f * x));
}
__device__ __forceinline__ float tanhap(float x) {
    float r; asm("tanh.approx.f32 %0,%1;" : "=f"(r) : "f"(x)); return r;
}
__device__ __forceinline__ unsigned ldacq(const unsigned* p) {
    unsigned v;
    asm volatile("ld.acquire.gpu.global.u32 %0,[%1];" : "=r"(v) : "l"(p) : "memory");
    return v;
}
__device__ __forceinline__ unsigned t32(float x) {
    unsigned r; asm("cvt.rna.tf32.f32 %0,%1;" : "=r"(r) : "f"(x)); return r;
}
__device__ __forceinline__ void mma8(float* c, const unsigned* a, const unsigned* b) {
    asm volatile(
        "mma.sync.aligned.m16n8k8.row.col.f32.tf32.tf32.f32 "
        "{%0,%1,%2,%3},{%4,%5,%6,%7},{%8,%9},{%0,%1,%2,%3};"
        : "+f"(c[0]), "+f"(c[1]), "+f"(c[2]), "+f"(c[3])
        : "r"(a[0]), "r"(a[1]), "r"(a[2]), "r"(a[3]), "r"(b[0]), "r"(b[1]));
}
__device__ __forceinline__ void cpa16(unsigned dst, const void* src) {
    asm volatile("cp.async.ca.shared.global [%0],[%1],16;" :: "r"(dst), "l"(src));
}
__device__ __forceinline__ void cpa_commit() {
    asm volatile("cp.async.commit_group;" ::: "memory");
}
template <int N>
__device__ __forceinline__ void cpa_wait() {
    asm volatile("cp.async.wait_group %0;" :: "n"(N) : "memory");
}

// ---------------------------------------------------------------------------
// tf32 tensor-core GEMM with 3-stage cp.async pipeline.
//   g_gx[m][n] = A_row(m).W[:,n] + bias[n],  M = TS*64, N = 1024.
//   CTA tile 128x128, k-chunk 32, triple-buffered dynamic smem,
//   ONE __syncthreads per chunk; stage c+2 overlaps compute of c.
// mode 0: A_row(m) = x + ((m&63)*TS + (m>>6))*128, K=128
// mode 1: A_row(m) = g_y0 + m*256,                 K=256
// ---------------------------------------------------------------------------
#define AS_STRIDE 36
#define BS_STRIDE 136
#define AS_BUF (128 * AS_STRIDE)          // floats per As stage
#define BS_BUF (32 * BS_STRIDE)           // floats per Bs stage
#define GEMM_SMEM ((3 * (AS_BUF + BS_BUF)) * 4)

__global__ void __launch_bounds__(256)
gemm_k(const float* __restrict__ A, const float* __restrict__ W,
       const float* __restrict__ bias, int K, int mode)
{
    extern __shared__ float smem[];
    float* AsB = smem;                    // [3][128][36]
    float* BsB = smem + 3 * AS_BUF;       // [3][32][136]

    const int tid  = threadIdx.x;
    const int lane = tid & 31;
    const int wid  = tid >> 5;
    const int wm   = wid & 1;
    const int wn   = wid >> 1;
    const int n0   = blockIdx.x * 128;
    const int m0   = blockIdx.y * 128;

    // A loader: row ar (2 threads/row), 16 floats at ak
    const int ar = tid >> 1, ak = (tid & 1) * 16;
    const int m = m0 + ar;
    const float* arow = mode ? (g_y0 + (size_t)m * 256)
                             : (A + ((size_t)(m & 63) * TS + (m >> 6)) * 128);
    // B loader: row bk (8 threads/row), 16 floats at bn
    const int bk = tid >> 3, bn = (tid & 7) * 16;
    const float* wrow = W + (size_t)bk * 1024 + n0 + bn;

    const unsigned as_dst0 = (unsigned)__cvta_generic_to_shared(&AsB[ar * AS_STRIDE + ak]);
    const unsigned bs_dst0 = (unsigned)__cvta_generic_to_shared(&BsB[bk * BS_STRIDE + bn]);

    const int NC = K >> 5;                // chunks of 32

    // stage chunk c into buffer c%3
    auto stage = [&](int c) {
        const unsigned ad = as_dst0 + (unsigned)((c % 3) * AS_BUF * 4);
        const unsigned bd = bs_dst0 + (unsigned)((c % 3) * BS_BUF * 4);
        const float* as = arow + c * 32 + ak;
        const float* bs = wrow + (size_t)(c * 32) * 1024;
#pragma unroll
        for (int q = 0; q < 4; ++q) {
            cpa16(ad + q * 16, as + 4 * q);
            cpa16(bd + q * 16, bs + 4 * q);
        }
        cpa_commit();
    };

    float acc[16][4];
#pragma unroll
    for (int i = 0; i < 16; ++i)
#pragma unroll
        for (int j = 0; j < 4; ++j) acc[i][j] = 0.f;

    stage(0);
    if (NC > 1) stage(1);

#pragma unroll 1
    for (int c = 0; c < NC; ++c) {
        if (c + 2 < NC) stage(c + 2);
        if (c + 2 < NC)      cpa_wait<2>();
        else if (c + 1 < NC) cpa_wait<1>();
        else                 cpa_wait<0>();
        __syncthreads();

        const float* As = AsB + (c % 3) * AS_BUF;
        const float* Bs = BsB + (c % 3) * BS_BUF;

#pragma unroll
        for (int k8 = 0; k8 < 32; k8 += 8) {
            unsigned af[4][4], bf[4][2];
            const int kk = k8 + (lane & 3);
#pragma unroll
            for (int i = 0; i < 4; ++i) {
                const int row = wm * 64 + i * 16 + (lane >> 2);
                af[i][0] = t32(As[row * AS_STRIDE + kk]);
                af[i][1] = t32(As[(row + 8) * AS_STRIDE + kk]);
                af[i][2] = t32(As[row * AS_STRIDE + kk + 4]);
                af[i][3] = t32(As[(row + 8) * AS_STRIDE + kk + 4]);
            }
#pragma unroll
            for (int j = 0; j < 4; ++j) {
                const int col = wn * 32 + j * 8 + (lane >> 2);
                bf[j][0] = t32(Bs[kk * BS_STRIDE + col]);
                bf[j][1] = t32(Bs[(kk + 4) * BS_STRIDE + col]);
            }
#pragma unroll
            for (int i = 0; i < 4; ++i)
#pragma unroll
                for (int j = 0; j < 4; ++j)
                    mma8(acc[i * 4 + j], af[i], bf[j]);
        }
        __syncthreads();     // buffer c%3 free for stage(c+3)... (3-buf safety)
    }

#pragma unroll
    for (int j = 0; j < 4; ++j) {
        const int col = n0 + wn * 32 + j * 8 + 2 * (lane & 3);
        float2 bb = *(const float2*)&bias[col];
#pragma unroll
        for (int i = 0; i < 4; ++i) {
            const int row = m0 + wm * 64 + i * 16 + (lane >> 2);
            const float* c = acc[i * 4 + j];
            float2 v0 = make_float2(c[0] + bb.x, c[1] + bb.y);
            float2 v1 = make_float2(c[2] + bb.x, c[3] + bb.y);
            *(float2*)&g_gx[(size_t)row * 1024 + col] = v0;
            *(float2*)&g_gx[(size_t)(row + 8) * 1024 + col] = v1;
        }
    }
}

// ---------------------------------------------------------------------------
// Recurrence: VERBATIM R15 (best known: 4.75 ms/layer).
// ---------------------------------------------------------------------------
__global__ void __launch_bounds__(256, 1)
recur_k(const float* __restrict__ whh, float* __restrict__ out, int layer)
{
    __shared__ __align__(16) float hsm[2][32][4];   // own-rank h [buf][ul][b]

    const int tid  = threadIdx.x;
    const int w    = tid >> 5;
    const int lane = tid & 31;
    const int grp  = blockIdx.x >> 3;
    const int r    = blockIdx.x & 7;
    const int gb0  = grp * 4;

    const int cp = lane >> 2;
    const int b  = lane & 3;
    const int gp = cp & 1;
    const int u  = cp >> 1;
    const int jj = r * 32 + w * 4 + u;
    const int colA = (2 * gp) * 256 + jj;

    ull wreg[8][8];
#pragma unroll
    for (int i = 0; i < 8; ++i) {
        const int k = ((r + i) & 7) * 32 + lane;
#pragma unroll
        for (int cpi = 0; cpi < 8; ++cpi) {
            const int cA = (2 * (cpi & 1)) * 256 + r * 32 + w * 4 + (cpi >> 1);
            const float* wp = whh + (size_t)k * 1024 + cA;
            wreg[i][cpi] = pk(wp[0], wp[256]);
        }
    }

    unsigned* myflag = &g_flag[layer][grp][r][0];
    unsigned* fin    = &g_fin[layer][grp][0];

    float cst = 0.f;
    float* yout = layer ? out : g_y0;
    float* hn = out + Y1_ELEMS + (size_t)layer * 16384;
    float* cn = out + Y1_ELEMS + 32768 + (size_t)layer * 16384;

    ((float*)hsm)[tid] = 0.f;
    __syncthreads();

    ull gxr, gxn = 0ull;
    {
        const float* gpx = g_gx + ((size_t)(TS - 1) * 64 + gb0 + b) * 1024 + colA;
        gxr = pk(__ldg(gpx), __ldg(gpx + 256));
    }

#pragma unroll 1
    for (int s = 0; s < TS; ++s) {
        const int cur = s & 1;
        const int nxt = cur ^ 1;

        if (s + 1 < TS) {
            const float* gpx = g_gx + ((size_t)(TS - 2 - s) * 64 + gb0 + b) * 1024 + colA;
            gxn = pk(__ldg(gpx), __ldg(gpx + 256));
        }

        ull v[32];
        // chunk 0: OWN rank from smem — gated only by the producer bar
        {
            float4 h4 = *(const float4*)&hsm[cur][lane][0];
            ull hd0 = dup2(h4.x), hd1 = dup2(h4.y), hd2 = dup2(h4.z), hd3 = dup2(h4.w);
#pragma unroll
            for (int cpi = 0; cpi < 8; ++cpi) {
                v[cpi * 4 + 0] = mul2(hd0, wreg[0][cpi]);
                v[cpi * 4 + 1] = mul2(hd1, wreg[0][cpi]);
                v[cpi * 4 + 2] = mul2(hd2, wreg[0][cpi]);
                v[cpi * 4 + 3] = mul2(hd3, wreg[0][cpi]);
            }
        }

        // per-warp wait: lanes 0..7 poll remote flags (own rank skipped)
        if (s) {
            if (lane < 8 && lane != r) {
                const unsigned tgt = (unsigned)s;
                const unsigned* fp = &g_flag[layer][grp][lane][0];
#pragma unroll 1
                while (ldacq(fp) < tgt) { }
            }
            __syncwarp();
        }

        // chunks 1..7: back-to-back ldcgs (MLP=7), then fma blocks
#pragma unroll
        for (int i = 1; i < 8; ++i) {
            float4 h4 = make_float4(0.f, 0.f, 0.f, 0.f);
            if (s) h4 = __ldcg((const float4*)&g_hx[cur][grp][((r + i) & 7) * 32 + lane][0]);
            ull hd0 = dup2(h4.x), hd1 = dup2(h4.y), hd2 = dup2(h4.z), hd3 = dup2(h4.w);
#pragma unroll
            for (int cpi = 0; cpi < 8; ++cpi) {
                v[cpi * 4 + 0] = fma2(hd0, wreg[i][cpi], v[cpi * 4 + 0]);
                v[cpi * 4 + 1] = fma2(hd1, wreg[i][cpi], v[cpi * 4 + 1]);
                v[cpi * 4 + 2] = fma2(hd2, wreg[i][cpi], v[cpi * 4 + 2]);
                v[cpi * 4 + 3] = fma2(hd3, wreg[i][cpi], v[cpi * 4 + 3]);
            }
        }

        // reduce-scatter butterfly: lane l ends holding (cp=l>>2, b=l&3)
#pragma unroll
        for (int t = 0; t < 5; ++t) {
            const int mybit = (lane >> t) & 1;
            const int n = 32 >> t;
#pragma unroll
            for (int i = 0; i < 16; ++i) {
                if (i < (n >> 1)) {
                    ull lo = v[2 * i], hi = v[2 * i + 1];
                    ull send = mybit ? lo : hi;
                    ull recv = __shfl_xor_sync(0xffffffffu, send, 1 << t);
                    v[i] = add2(mybit ? hi : lo, recv);
                }
            }
        }

        // epilogue
        float h1 = 0.f;
        {
            float p0, p1;
            upk(add2(v[0], gxr), p0, p1);
            float a0 = sigf(p0);
            float a1 = gp ? tanhap(p1) : sigf(p1);
            ull other = __shfl_xor_sync(0xffffffffu, pk(a0, a1), 4);
            if (gp == 0) {
                float so, tg; upk(other, so, tg);
                cst = a0 * cst + a1 * tg;
                h1 = so * tanhap(cst);
            }
        }
        gxr = gxn;

        // coalesced h publish: gather unit u's 4 batch values into lane 8u
        {
            float4 hv;
            const int base = lane & 24;
            hv.x = __shfl_sync(0xffffffffu, h1, base);
            hv.y = __shfl_sync(0xffffffffu, h1, base + 1);
            hv.z = __shfl_sync(0xffffffffu, h1, base + 2);
            hv.w = __shfl_sync(0xffffffffu, h1, base + 3);
            if ((lane & 7) == 0 && s < TS - 1) {
                const int row = r * 32 + w * 4 + (lane >> 3);
                *(float4*)&g_hx[nxt][grp][row][0] = hv;            // 1 STG.128
                *(float4*)&hsm[nxt][w * 4 + (lane >> 3)][0] = hv;  // 1 STS.128
            }
        }

        __syncthreads();              // h stores happen-before the release
        if (s < TS - 1 && tid == 0)
            asm volatile("st.release.gpu.global.u32 [%0], %1;"
                         :: "l"(myflag), "r"((unsigned)(s + 1)) : "memory");

        // outputs AFTER the publish — off the critical chain
        if (gp == 0) {
            yout[((size_t)s * 64 + gb0 + b) * 256 + jj] = h1;
            if (s == TS - 1) {
                size_t hi_ = (size_t)(gb0 + b) * 256 + jj;
                hn[hi_] = h1; cn[hi_] = cst;
            }
        }
    }

    // reset flags for the next graph replay (deterministic launches)
    __syncthreads();
    if (tid == 0) {
        asm volatile("red.release.gpu.global.add.u32 [%0], 1;" :: "l"(fin) : "memory");
        if (r == 0) {
#pragma unroll 1
            while (ldacq(fin) < 8u) { }
#pragma unroll
            for (int d = 0; d < 8; ++d)
                asm volatile("st.global.u32 [%0], %1;"
                             :: "l"(&g_flag[layer][grp][d][0]), "r"(0u) : "memory");
            asm volatile("st.global.u32 [%0], %1;" :: "l"(fin), "r"(0u) : "memory");
        }
    }
}

extern "C" void kernel_launch(void* const* d_in, const int* in_sizes, int n_in,
                              void* d_out, int out_size)
{
    const float* x    = (const float*)d_in[0];
    const float* wih0 = (const float*)d_in[1];
    const float* whh0 = (const float*)d_in[2];
    const float* b0   = (const float*)d_in[3];
    const float* wih1 = (const float*)d_in[4];
    const float* whh1 = (const float*)d_in[5];
    const float* b1   = (const float*)d_in[6];
    float* out = (float*)d_out;

    static int smem_set = 0;
    if (!smem_set) {
        cudaFuncSetAttribute(gemm_k, cudaFuncAttributeMaxDynamicSharedMemorySize,
                             GEMM_SMEM);
        smem_set = 1;
    }

    dim3 gg(8, 1024);
    gemm_k<<<gg, 256, GEMM_SMEM>>>(x, wih0, b0, 128, 0);
    recur_k<<<128, 256>>>(whh0, out, 0);
    gemm_k<<<gg, 256, GEMM_SMEM>>>(x, wih1, b1, 256, 1);
    recur_k<<<128, 256>>>(whh1, out, 1);
}